// round 1
// baseline (speedup 1.0000x reference)
#include <cuda_runtime.h>
#include <cuda_bf16.h>

// time_embeddings: out[b, i] = sin/cos(time[b] * 10000^(-2*(i//2)/1280))
// even i -> sin, odd i -> cos.
//
// Pure store-bandwidth-bound producer: 65536 x 1280 fp32 = 335.5 MB out.
// Strategy:
//   - 320 threads/block, thread t owns columns [4t, 4t+3] (one float4).
//   - dims 4t,4t+1 share rate r0 (pair p0=2t); dims 4t+2,4t+3 share r1 (p1=2t+1).
//     => one sincosf per pair gives both sin and cos outputs.
//   - rates computed ONCE per thread via exp2f, amortized over 8 rows/block.
//   - float4 stores: consecutive threads -> consecutive 16B -> perfect STG.128
//     coalescing.

static constexpr int DIM            = 1280;
static constexpr int VEC4           = DIM / 4;   // 320 float4 per row
static constexpr int ROWS_PER_BLOCK = 8;

__global__ __launch_bounds__(VEC4)
void time_emb_kernel(const float* __restrict__ time,
                     float4* __restrict__ out,
                     int batch)
{
    const int col = threadIdx.x;        // 0..319
    const int p0  = 2 * col;            // pair index for dims 4c, 4c+1
    // rate(p) = 10000^(-p/640) = exp2(-p * log2(10000)/640)
    const float C  = 0.02076205059304601f;   // log2(10000) / 640
    const float r0 = exp2f(-(float)p0 * C);
    const float r1 = exp2f(-(float)(p0 + 1) * C);

    const int row_base = blockIdx.x * ROWS_PER_BLOCK;

    #pragma unroll
    for (int r = 0; r < ROWS_PER_BLOCK; ++r) {
        const int row = row_base + r;
        if (row >= batch) break;
        const float t = __ldg(&time[row]);   // broadcast within block, L2-resident
        float s0, c0, s1, c1;
        sincosf(t * r0, &s0, &c0);
        sincosf(t * r1, &s1, &c1);
        out[(size_t)row * VEC4 + col] = make_float4(s0, c0, s1, c1);
    }
}

extern "C" void kernel_launch(void* const* d_in, const int* in_sizes, int n_in,
                              void* d_out, int out_size)
{
    const float* time = (const float*)d_in[0];
    float4* out = (float4*)d_out;
    const int batch = in_sizes[0];

    const int grid = (batch + ROWS_PER_BLOCK - 1) / ROWS_PER_BLOCK;
    time_emb_kernel<<<grid, VEC4>>>(time, out, batch);
}

// round 2
// speedup vs baseline: 1.0596x; 1.0596x over previous
#include <cuda_runtime.h>
#include <cuda_bf16.h>

// time_embeddings: out[b, i] = sin/cos(time[b] * 10000^(-2*(i//2)/1280))
// even i -> sin, odd i -> cos.
//
// R2: replace accurate sincosf (~35-40 SASS / pair, issue-bound at 85%) with
// hardware MUFU __sinf/__cosf (~2 SASS each). Angles are bounded by 1000 rad,
// where the fast-path range reduction error is ~1e-4 abs -- well inside the
// 1e-3 rel_err budget. Stores go through __stcs (streaming, evict-first):
// 335 MB output (2.7x L2) is never re-read, so don't thrash L2 with it.

static constexpr int DIM            = 1280;
static constexpr int VEC4           = DIM / 4;   // 320 float4 per row
static constexpr int ROWS_PER_BLOCK = 8;

__global__ __launch_bounds__(VEC4)
void time_emb_kernel(const float* __restrict__ time,
                     float4* __restrict__ out,
                     int batch)
{
    const int col = threadIdx.x;        // 0..319
    const int p0  = 2 * col;            // pair index for dims 4c, 4c+1
    // rate(p) = 10000^(-p/640) = exp2(-p * log2(10000)/640)
    const float C  = 0.02076205059304601f;   // log2(10000) / 640
    const float r0 = exp2f(-(float)p0 * C);
    const float r1 = exp2f(-(float)(p0 + 1) * C);

    const int row_base = blockIdx.x * ROWS_PER_BLOCK;
    float4* dst = out + (size_t)row_base * VEC4 + col;

    #pragma unroll
    for (int r = 0; r < ROWS_PER_BLOCK; ++r) {
        const int row = row_base + r;
        if (row >= batch) break;
        const float t  = __ldg(&time[row]);   // broadcast within block
        const float a0 = t * r0;
        const float a1 = t * r1;
        float4 v;
        v.x = __sinf(a0);
        v.y = __cosf(a0);
        v.z = __sinf(a1);
        v.w = __cosf(a1);
        __stcs(dst, v);                       // streaming store, evict-first
        dst += VEC4;
    }
}

extern "C" void kernel_launch(void* const* d_in, const int* in_sizes, int n_in,
                              void* d_out, int out_size)
{
    const float* time = (const float*)d_in[0];
    float4* out = (float4*)d_out;
    const int batch = in_sizes[0];

    const int grid = (batch + ROWS_PER_BLOCK - 1) / ROWS_PER_BLOCK;
    time_emb_kernel<<<grid, VEC4>>>(time, out, batch);
}